// round 4
// baseline (speedup 1.0000x reference)
#include <cuda_runtime.h>
#include <cuda_bf16.h>

// HashGrid trilinear interpolation with analytic gradient.
// Inputs:  x (N,3) f32, feat_params (CAP=20000, 520, 5) f32, block_table (32,32,32) i32
// Outputs (flat f32 concat): feats (N,5) | dfeats_dx (N,5,3) | masks (N) as 0/1
// Constants: R=8, V=0.01, G=32, F=5, STRIDE=520, OFFSET=0
//
// NOTE on u = x / V: under jax.jit, XLA rewrites divide-by-constant into
// multiply-by-reciprocal with the reciprocal folded at compile time:
// 1/0.01f rounds to exactly 100.0f. So the reference effectively computes
// u = x * 100.0f. We must match this bitwise — cell assignment (floor) is
// discontinuous and the gradient output flips O(1) at boundary points.

#define HG_N 2000000
#define HG_F 5
#define HG_STRIDE 520
#define HG_G 32

__global__ __launch_bounds__(256)
void hashgrid_kernel(const float* __restrict__ x,
                     const float* __restrict__ feat,
                     const int*   __restrict__ btab,
                     float*       __restrict__ out,
                     int n)
{
    int i = blockIdx.x * blockDim.x + threadIdx.x;
    if (i >= n) return;

    // u = x * 100.0f (matches XLA's divide-by-constant rewrite bitwise)
    float u0 = x[3 * i + 0] * 100.0f;
    float u1 = x[3 * i + 1] * 100.0f;
    float u2 = x[3 * i + 2] * 100.0f;

    float fl0 = floorf(u0), fl1 = floorf(u1), fl2 = floorf(u2);
    int xi0 = (int)fl0, xi1 = (int)fl1, xi2 = (int)fl2;
    float fr0 = u0 - fl0, fr1 = u1 - fl1, fr2 = u2 - fl2;

    // Per-corner block index + voxel index. gv >= 0 always (x in [0, 2.56)),
    // so >>3 / &7 implement floor_divide / mod exactly.
    int bidxA[8];
    int vidxA[8];
    bool maskAll = true;

    #pragma unroll
    for (int c = 0; c < 8; c++) {
        int ci = (c >> 2) & 1, cj = (c >> 1) & 1, ck = c & 1;
        int gx = xi0 + ci, gy = xi1 + cj, gz = xi2 + ck;
        int bx = gx >> 3, by = gy >> 3, bz = gz >> 3;
        bool inb = (bx < HG_G) & (by < HG_G) & (bz < HG_G);
        int bidx = -1;
        if (inb) {
            bidx = btab[(bx * HG_G + by) * HG_G + bz];
        }
        bidxA[c] = bidx;
        vidxA[c] = ((gx & 7) * 8 + (gy & 7)) * 8 + (gz & 7);
        maskAll &= (bidx >= 0);
    }

    float acc[HG_F]  = {0.f, 0.f, 0.f, 0.f, 0.f};
    float d0[HG_F]   = {0.f, 0.f, 0.f, 0.f, 0.f};
    float d1[HG_F]   = {0.f, 0.f, 0.f, 0.f, 0.f};
    float d2[HG_F]   = {0.f, 0.f, 0.f, 0.f, 0.f};

    if (maskAll) {
        // trilinear weights: w01 = {1-frac, frac}, sign = {-1, +1}
        float wx[2] = {1.0f - fr0, fr0};
        float wy[2] = {1.0f - fr1, fr1};
        float wz[2] = {1.0f - fr2, fr2};
        const float sgn[2] = {-1.0f, 1.0f};

        #pragma unroll
        for (int c = 0; c < 8; c++) {
            int ci = (c >> 2) & 1, cj = (c >> 1) & 1, ck = c & 1;
            float pwx = wx[ci], pwy = wy[cj], pwz = wz[ck];
            float w   = pwx * pwy * pwz;
            float dwx = sgn[ci] * pwy * pwz;
            float dwy = pwx * sgn[cj] * pwz;
            float dwz = pwx * pwy * sgn[ck];

            int base = (bidxA[c] * HG_STRIDE + vidxA[c]) * HG_F;
            #pragma unroll
            for (int f = 0; f < HG_F; f++) {
                float v = __ldg(&feat[base + f]);
                acc[f] += w   * v;
                d0[f]  += dwx * v;
                d1[f]  += dwy * v;
                d2[f]  += dwz * v;
            }
        }
    }

    // Outputs: feats (N,5) | dfeats (N,5,3) * 100 | mask (N)
    const float invV = 100.0f;   // matches XLA's folded reciprocal of 0.01f
    size_t featBase  = (size_t)i * HG_F;
    size_t dBase     = (size_t)HG_N * HG_F + (size_t)i * (HG_F * 3);
    size_t mBase     = (size_t)HG_N * HG_F + (size_t)HG_N * (HG_F * 3);

    #pragma unroll
    for (int f = 0; f < HG_F; f++) {
        out[featBase + f] = acc[f];           // zero if !maskAll (acc stays 0)
        out[dBase + f * 3 + 0] = d0[f] * invV;
        out[dBase + f * 3 + 1] = d1[f] * invV;
        out[dBase + f * 3 + 2] = d2[f] * invV;
    }
    out[mBase + i] = maskAll ? 1.0f : 0.0f;
}

extern "C" void kernel_launch(void* const* d_in, const int* in_sizes, int n_in,
                              void* d_out, int out_size)
{
    const float* x    = (const float*)d_in[0];
    const float* feat = (const float*)d_in[1];
    const int*   btab = (const int*)d_in[2];
    float*       out  = (float*)d_out;

    int n = in_sizes[0] / 3;   // x has N*3 elements
    int threads = 256;
    int blocks  = (n + threads - 1) / threads;
    hashgrid_kernel<<<blocks, threads>>>(x, feat, btab, out, n);
}

// round 6
// speedup vs baseline: 1.3711x; 1.3711x over previous
#include <cuda_runtime.h>
#include <cuda_bf16.h>

// HashGrid trilinear interpolation with analytic gradient.
// Inputs:  x (N,3) f32, feat_params (CAP=20000, 520, 5) f32, block_table (32,32,32) i32
// Outputs (flat f32 concat): feats (N,5) | dfeats_dx (N,5,3) | masks (N) as 0/1
// Constants: R=8, V=0.01, G=32, F=5, STRIDE=520, OFFSET=0
//
// u = x * 100.0f matches XLA's divide-by-constant rewrite bitwise (verified
// rel_err == 0.0). Do not change the arithmetic.

#define HG_N 2000000
#define HG_F 5
#define HG_G 32
#define HG_BLOCKF (520 * 5)                 // floats per block entry
#define HG_TOTALF (20000 * 520 * 5)         // total floats in feat_params

__device__ __forceinline__ int btab_lookup(const int* __restrict__ btab,
                                           int bx, int by, int bz)
{
    // bx,by,bz in [0,32]; valid iff all < 32  <=>  bit 5 clear in the OR
    if (((bx | by | bz) >> 5) == 0)
        return __ldg(&btab[(bx * HG_G + by) * HG_G + bz]);
    return -1;
}

// Load 5 floats starting at feat[base] via two aligned LDG.128 + selects.
// Safe: base <= HG_TOTALF-5 and HG_TOTALF % 4 == 0  =>  (base&~3)+8 <= HG_TOTALF.
__device__ __forceinline__ void load5(const float* __restrict__ feat, int base,
                                      float r[5])
{
    int a   = base & ~3;
    int off = base & 3;
    float4 q0 = __ldg(reinterpret_cast<const float4*>(feat + a));
    float4 q1 = __ldg(reinterpret_cast<const float4*>(feat + a + 4));
    if (off == 0)      { r[0]=q0.x; r[1]=q0.y; r[2]=q0.z; r[3]=q0.w; r[4]=q1.x; }
    else if (off == 1) { r[0]=q0.y; r[1]=q0.z; r[2]=q0.w; r[3]=q1.x; r[4]=q1.y; }
    else if (off == 2) { r[0]=q0.z; r[1]=q0.w; r[2]=q1.x; r[3]=q1.y; r[4]=q1.z; }
    else               { r[0]=q0.w; r[1]=q1.x; r[2]=q1.y; r[3]=q1.z; r[4]=q1.w; }
}

__global__ __launch_bounds__(256)
void hashgrid_kernel(const float* __restrict__ x,
                     const float* __restrict__ feat,
                     const int*   __restrict__ btab,
                     float*       __restrict__ out,
                     int n)
{
    __shared__ float sA[256 * 5];    // feats
    __shared__ float sB[256 * 15];   // dfeats
    __shared__ float sC[256];        // masks

    const int blk = blockIdx.x;
    const int tid = threadIdx.x;
    const int i   = blk * 256 + tid;
    const int cnt = min(256, n - blk * 256);

    if (tid < cnt) {
        // ---- cell / weights (bit-identical to reference) ----
        float u0 = x[3 * i + 0] * 100.0f;
        float u1 = x[3 * i + 1] * 100.0f;
        float u2 = x[3 * i + 2] * 100.0f;

        float fl0 = floorf(u0), fl1 = floorf(u1), fl2 = floorf(u2);
        int xi0 = (int)fl0, xi1 = (int)fl1, xi2 = (int)fl2;
        float fr0 = u0 - fl0, fr1 = u1 - fl1, fr2 = u2 - fl2;

        // ---- block indices with dedup (corner 000 always in-bounds) ----
        int bx0 = xi0 >> 3, by0 = xi1 >> 3, bz0 = xi2 >> 3;
        bool cx = (xi0 & 7) == 7, cy = (xi1 & 7) == 7, cz = (xi2 & 7) == 7;
        int bx1 = (xi0 + 1) >> 3, by1 = (xi1 + 1) >> 3, bz1 = (xi2 + 1) >> 3;

        int t000 = __ldg(&btab[(bx0 * HG_G + by0) * HG_G + bz0]);

        int bidxA[8];
        bidxA[0] = t000;
        bidxA[1] = cz             ? btab_lookup(btab, bx0, by0, bz1) : t000;
        bidxA[2] = cy             ? btab_lookup(btab, bx0, by1, bz0) : t000;
        bidxA[3] = (cy || cz)     ? btab_lookup(btab, bx0, by1, bz1) : t000;
        bidxA[4] = cx             ? btab_lookup(btab, bx1, by0, bz0) : t000;
        bidxA[5] = (cx || cz)     ? btab_lookup(btab, bx1, by0, bz1) : t000;
        bidxA[6] = (cx || cy)     ? btab_lookup(btab, bx1, by1, bz0) : t000;
        bidxA[7] = (cx || cy || cz) ? btab_lookup(btab, bx1, by1, bz1) : t000;

        bool maskAll = true;
        #pragma unroll
        for (int c = 0; c < 8; c++) maskAll &= (bidxA[c] >= 0);

        float acc[5] = {0.f, 0.f, 0.f, 0.f, 0.f};
        float d0[5]  = {0.f, 0.f, 0.f, 0.f, 0.f};
        float d1[5]  = {0.f, 0.f, 0.f, 0.f, 0.f};
        float d2[5]  = {0.f, 0.f, 0.f, 0.f, 0.f};

        if (maskAll) {
            float wx[2] = {1.0f - fr0, fr0};
            float wy[2] = {1.0f - fr1, fr1};
            float wz[2] = {1.0f - fr2, fr2};
            const float sgn[2] = {-1.0f, 1.0f};

            #pragma unroll
            for (int c = 0; c < 8; c++) {
                int ci = (c >> 2) & 1, cj = (c >> 1) & 1, ck = c & 1;
                int lx = (xi0 + ci) & 7, ly = (xi1 + cj) & 7, lz = (xi2 + ck) & 7;
                int vidx = (lx * 8 + ly) * 8 + lz;
                int base = bidxA[c] * HG_BLOCKF + vidx * 5;

                float v[5];
                load5(feat, base, v);

                float pwx = wx[ci], pwy = wy[cj], pwz = wz[ck];
                float w   = pwx * pwy * pwz;
                float dwx = sgn[ci] * pwy * pwz;
                float dwy = pwx * sgn[cj] * pwz;
                float dwz = pwx * pwy * sgn[ck];

                #pragma unroll
                for (int f = 0; f < 5; f++) {
                    acc[f] += w   * v[f];
                    d0[f]  += dwx * v[f];
                    d1[f]  += dwy * v[f];
                    d2[f]  += dwz * v[f];
                }
            }
        }

        // ---- stage into shared (odd strides -> bank-conflict-free) ----
        const float invV = 100.0f;
        #pragma unroll
        for (int f = 0; f < 5; f++) {
            sA[tid * 5 + f]          = acc[f];
            sB[tid * 15 + f * 3 + 0] = d0[f] * invV;
            sB[tid * 15 + f * 3 + 1] = d1[f] * invV;
            sB[tid * 15 + f * 3 + 2] = d2[f] * invV;
        }
        sC[tid] = maskAll ? 1.0f : 0.0f;
    }

    __syncthreads();

    // ---- coalesced float4 copy smem -> gmem ----
    {
        // feats: global floats [blk*1280, blk*1280 + cnt*5)
        float* g = out + (size_t)blk * (256 * 5);
        int tot = cnt * 5;
        for (int k = tid * 4; k + 3 < tot; k += 256 * 4)
            *reinterpret_cast<float4*>(g + k) = *reinterpret_cast<const float4*>(sA + k);
        for (int k = (tot & ~3) + tid; k < tot; k += 256)
            g[k] = sA[k];
    }
    {
        // dfeats: global floats [N*5 + blk*3840, ... + cnt*15)
        float* g = out + (size_t)HG_N * 5 + (size_t)blk * (256 * 15);
        int tot = cnt * 15;
        for (int k = tid * 4; k + 3 < tot; k += 256 * 4)
            *reinterpret_cast<float4*>(g + k) = *reinterpret_cast<const float4*>(sB + k);
        for (int k = (tot & ~3) + tid; k < tot; k += 256)
            g[k] = sB[k];
    }
    {
        // masks: global floats [N*20 + blk*256, ... + cnt)
        float* g = out + (size_t)HG_N * 20 + (size_t)blk * 256;
        int tot = cnt;
        for (int k = tid * 4; k + 3 < tot; k += 256 * 4)
            *reinterpret_cast<float4*>(g + k) = *reinterpret_cast<const float4*>(sC + k);
        for (int k = (tot & ~3) + tid; k < tot; k += 256)
            g[k] = sC[k];
    }
}

extern "C" void kernel_launch(void* const* d_in, const int* in_sizes, int n_in,
                              void* d_out, int out_size)
{
    const float* x    = (const float*)d_in[0];
    const float* feat = (const float*)d_in[1];
    const int*   btab = (const int*)d_in[2];
    float*       out  = (float*)d_out;

    int n = in_sizes[0] / 3;   // x has N*3 elements
    int blocks = (n + 255) / 256;
    hashgrid_kernel<<<blocks, 256>>>(x, feat, btab, out, n);
}